// round 16
// baseline (speedup 1.0000x reference)
#include <cuda_runtime.h>
#include <cuda_bf16.h>
#include <cuda_fp16.h>
#include <math.h>

#define NTOK 1024
#define CQ   768
#define CZ   128
#define NH   16
#define HD   48

// ---------------- scratch (static device memory) ----------------
__device__ float g_q   [NTOK * CQ];
__device__ float g_k   [NTOK * CQ];
__device__ float g_v   [NTOK * CQ];
__device__ float g_gate[NTOK * CQ];
__device__ float g_og  [NTOK * CQ];
__device__ __half g_sc [(size_t)NTOK * NH * NTOK];   // pair+mask bias (half), layout [i][h][j]
__device__ float g_wp  [CZ * NH];
__device__ float g_wpT [NH * 132];
__device__ float g_Wh  [NH];
__device__ float g_ch  [NH];
__device__ float g_mu  [NTOK];
__device__ float g_rs  [NTOK];

// ---------------- helpers ----------------
__device__ __forceinline__ unsigned f2tf(float x) {
    unsigned u; asm("cvt.rna.tf32.f32 %0, %1;" : "=r"(u) : "f"(x)); return u;
}
__device__ __forceinline__ float tf32f(float x) { return __uint_as_float(f2tf(x)); }
__device__ __forceinline__ unsigned su(float x) { return __float_as_uint(x); }

// pack (even k -> low half, odd k -> high half), hi/lo bf16 split
__device__ __forceinline__ void bfsplit2(float e, float o, unsigned& hw, unsigned& lw) {
    __nv_bfloat162 h2, l2;
    h2.x = __float2bfloat16_rn(e);
    h2.y = __float2bfloat16_rn(o);
    l2.x = __float2bfloat16_rn(e - __bfloat162float(h2.x));
    l2.y = __float2bfloat16_rn(o - __bfloat162float(h2.y));
    hw = *(unsigned*)&h2;
    lw = *(unsigned*)&l2;
}

#define MMA_TF32(c, a, b0_, b1_)                                              \
    asm volatile("mma.sync.aligned.m16n8k8.row.col.f32.tf32.tf32.f32 "        \
                 "{%0,%1,%2,%3}, {%4,%5,%6,%7}, {%8,%9}, {%0,%1,%2,%3};"      \
                 : "+f"(c[0]), "+f"(c[1]), "+f"(c[2]), "+f"(c[3])             \
                 : "r"(a[0]), "r"(a[1]), "r"(a[2]), "r"(a[3]),                \
                   "r"(b0_), "r"(b1_));

#define MMA_BF16(c, a, b0_, b1_)                                              \
    asm volatile("mma.sync.aligned.m16n8k16.row.col.f32.bf16.bf16.f32 "       \
                 "{%0,%1,%2,%3}, {%4,%5,%6,%7}, {%8,%9}, {%0,%1,%2,%3};"      \
                 : "+f"(c[0]), "+f"(c[1]), "+f"(c[2]), "+f"(c[3])             \
                 : "r"(a[0]), "r"(a[1]), "r"(a[2]), "r"(a[3]),                \
                   "r"(b0_), "r"(b1_));

#define MMA_F16(c, a0_, a1_, a2_, a3_, b0_, b1_)                              \
    asm volatile("mma.sync.aligned.m16n8k16.row.col.f32.f16.f16.f32 "         \
                 "{%0,%1,%2,%3}, {%4,%5,%6,%7}, {%8,%9}, {%0,%1,%2,%3};"      \
                 : "+f"(c[0]), "+f"(c[1]), "+f"(c[2]), "+f"(c[3])             \
                 : "r"(a0_), "r"(a1_), "r"(a2_), "r"(a3_),                    \
                   "r"(b0_), "r"(b1_));

// ---------------- per-row LN stats of a ----------------
__global__ void __launch_bounds__(256) a_stats_kernel(const float* __restrict__ a) {
    int row = blockIdx.x;
    int tid = threadIdx.x;
    const float* x = a + (size_t)row * CQ;
    __shared__ float red[256];

    float xv[3];
    float s = 0.f;
#pragma unroll
    for (int k = 0; k < 3; k++) { xv[k] = x[tid + k * 256]; s += xv[k]; }
    red[tid] = s; __syncthreads();
    for (int st = 128; st > 0; st >>= 1) { if (tid < st) red[tid] += red[tid + st]; __syncthreads(); }
    float mu = red[0] * (1.f / CQ);
    __syncthreads();

    float s2 = 0.f;
#pragma unroll
    for (int k = 0; k < 3; k++) { float d = xv[k] - mu; s2 += d * d; }
    red[tid] = s2; __syncthreads();
    for (int st = 128; st > 0; st >>= 1) { if (tid < st) red[tid] += red[tid + st]; __syncthreads(); }
    if (tid == 0) {
        g_mu[row] = mu;
        g_rs[row] = rsqrtf(red[0] * (1.f / CQ) + 1e-5f);
    }
}

// ---------------- pair-bias precompute ----------------
__global__ void prep_kernel(const float* __restrict__ gz,
                            const float* __restrict__ bz,
                            const float* __restrict__ wz) {
    int tid = threadIdx.x;       // 128
    float gzc = gz[tid];
    for (int h = 0; h < NH; h++) {
        float w = gzc * wz[tid * NH + h];
        g_wp[tid * NH + h] = w;
        g_wpT[h * 132 + tid] = tf32f(w);
    }
    __syncthreads();
    if (tid < NH) {
        float W = 0.f, C = 0.f;
        for (int c = 0; c < CZ; c++) {
            W += g_wp[c * NH + tid];
            C += bz[c] * wz[c * NH + tid];
        }
        g_Wh[tid] = W;
        g_ch[tid] = C;
    }
}

// ---------------- pair bias via tensor cores (half output) ----------------
__global__ void __launch_bounds__(256) pair_mma(const float* __restrict__ z,
                                                const float* __restrict__ mask) {
    extern __shared__ float psm[];
    float* zs  = psm;                     // 128*132
    float* wpt = zs + 128 * 132;          // 16*132
    float* sb  = wpt + 16 * 132;          // 16*132
    float* mus = sb + 16 * 132;           // 128
    float* rss = mus + 128;               // 128

    int i  = blockIdx.y;
    int j0 = blockIdx.x * 128;
    int tid = threadIdx.x, lane = tid & 31, w = tid >> 5;
    int g = lane >> 2, t = lane & 3;

    for (int e = tid; e < NH * 132; e += 256) wpt[e] = g_wpT[e];

    int row = tid >> 1, c0 = (tid & 1) * 64;
    const float* zrow = z + ((size_t)i * NTOK + j0 + row) * CZ + c0;
    float s1 = 0.f, s2 = 0.f;
#pragma unroll
    for (int q = 0; q < 16; q++) {
        float4 v = *(const float4*)&zrow[q * 4];
        s1 += v.x + v.y + v.z + v.w;
        s2 += v.x * v.x + v.y * v.y + v.z * v.z + v.w * v.w;
        float4 hv = make_float4(tf32f(v.x), tf32f(v.y), tf32f(v.z), tf32f(v.w));
        *(float4*)&zs[row * 132 + c0 + q * 4] = hv;
    }
    s1 += __shfl_xor_sync(0xffffffffu, s1, 1);
    s2 += __shfl_xor_sync(0xffffffffu, s2, 1);
    float mu = s1 * (1.f / CZ);
    float var = s2 * (1.f / CZ) - mu * mu;
    float rs = rsqrtf(var + 1e-5f);
    if ((tid & 1) == 0) { mus[row] = mu; rss[row] = rs; }
    __syncthreads();

    int wr = w * 16;
    float c[2][4] = {};
#pragma unroll
    for (int ks = 0; ks < 16; ks++) {
        int kk = ks * 8;
        unsigned a[4];
        a[0] = su(zs[(wr + g) * 132 + kk + t]);
        a[1] = su(zs[(wr + g + 8) * 132 + kk + t]);
        a[2] = su(zs[(wr + g) * 132 + kk + t + 4]);
        a[3] = su(zs[(wr + g + 8) * 132 + kk + t + 4]);
#pragma unroll
        for (int nt = 0; nt < 2; nt++) {
            unsigned b0 = su(wpt[(nt * 8 + g) * 132 + kk + t]);
            unsigned b1 = su(wpt[(nt * 8 + g) * 132 + kk + t + 4]);
            MMA_TF32(c[nt], a, b0, b1);
        }
    }

    float muA = mus[wr + g], rsA = rss[wr + g];
    float muB = mus[wr + g + 8], rsB = rss[wr + g + 8];
#pragma unroll
    for (int nt = 0; nt < 2; nt++) {
#pragma unroll
        for (int cc = 0; cc < 2; cc++) {
            int h = nt * 8 + 2 * t + cc;
            float W = g_Wh[h], C0 = g_ch[h];
            sb[h * 132 + wr + g]     = rsA * (c[nt][cc]     - muA * W) + C0;
            sb[h * 132 + wr + g + 8] = rsB * (c[nt][cc + 2] - muB * W) + C0;
        }
    }
    __syncthreads();

    float mi = mask[i];
#pragma unroll
    for (int e = tid; e < NH * 64; e += 256) {
        int h = e >> 6, jp = e & 63;
        int j = 2 * jp;
        float mb0 = fmaxf(-30000.f, 1.0e9f * (mi * mask[j0 + j]     - 1.f));
        float mb1 = fmaxf(-30000.f, 1.0e9f * (mi * mask[j0 + j + 1] - 1.f));
        __half2 hv = __floats2half2_rn(sb[h * 132 + j] + mb0, sb[h * 132 + j + 1] + mb1);
        *(__half2*)&g_sc[((size_t)i * NH + h) * NTOK + j0 + j] = hv;
    }
}

// ================= 3xBF16-split GEMM, 128x64 tile, BK=16 (round-12 proven core) =================
template <int LN_A>
__device__ __forceinline__ void gemm_core_bf(const float* __restrict__ A,
                                             const float* __restrict__ B,
                                             const float* __restrict__ gw,
                                             const float* __restrict__ bw,
                                             float c[2][4][4],
                                             unsigned* sAh, unsigned* sAl,
                                             unsigned* sBh, unsigned* sBl) {
    int tid  = threadIdx.x;
    int lane = tid & 31, w = tid >> 5;
    int wm = w & 3, wn = w >> 2;
    int g = lane >> 2, t = lane & 3;
    int m0 = blockIdx.y * 128, n0 = blockIdx.x * 64;
    int arow = tid >> 1, akb = (tid & 1) * 8;
    int bp = tid >> 5, bn = lane * 2;

    float mu = 0.f, rs = 1.f;
    if (LN_A) { mu = g_mu[m0 + arow]; rs = g_rs[m0 + arow]; }
    const float* Arow = A + (size_t)(m0 + arow) * CQ;

    for (int k0 = 0; k0 < CQ; k0 += 16) {
        __syncthreads();
        {
            float4 v0 = *(const float4*)&Arow[k0 + akb];
            float4 v1 = *(const float4*)&Arow[k0 + akb + 4];
            float xs[8] = {v0.x, v0.y, v0.z, v0.w, v1.x, v1.y, v1.z, v1.w};
            if (LN_A) {
#pragma unroll
                for (int q = 0; q < 8; q++)
                    xs[q] = (xs[q] - mu) * rs * gw[k0 + akb + q] + bw[k0 + akb + q];
            }
#pragma unroll
            for (int q = 0; q < 4; q++) {
                unsigned hw, lw;
                bfsplit2(xs[2 * q], xs[2 * q + 1], hw, lw);
                int p = (akb >> 1) + q;
                sAh[p * 136 + arow] = hw;
                sAl[p * 136 + arow] = lw;
            }
        }
        {
            const float* Bp = &B[(size_t)(k0 + 2 * bp) * CQ + n0 + bn];
            float2 r0 = *(const float2*)Bp;
            float2 r1 = *(const float2*)(Bp + CQ);
            unsigned hw0, lw0, hw1, lw1;
            bfsplit2(r0.x, r1.x, hw0, lw0);
            bfsplit2(r0.y, r1.y, hw1, lw1);
            *(uint2*)&sBh[bp * 72 + bn] = make_uint2(hw0, hw1);
            *(uint2*)&sBl[bp * 72 + bn] = make_uint2(lw0, lw1);
        }
        __syncthreads();

        unsigned Ah[2][4], Al[2][4], Bh[4][2], Bl[4][2];
#pragma unroll
        for (int mt = 0; mt < 2; mt++) {
            int mb = wm * 32 + mt * 16 + g;
            Ah[mt][0] = sAh[t * 136 + mb];
            Ah[mt][1] = sAh[t * 136 + mb + 8];
            Ah[mt][2] = sAh[(t + 4) * 136 + mb];
            Ah[mt][3] = sAh[(t + 4) * 136 + mb + 8];
            Al[mt][0] = sAl[t * 136 + mb];
            Al[mt][1] = sAl[t * 136 + mb + 8];
            Al[mt][2] = sAl[(t + 4) * 136 + mb];
            Al[mt][3] = sAl[(t + 4) * 136 + mb + 8];
        }
#pragma unroll
        for (int nt = 0; nt < 4; nt++) {
            int nb = wn * 32 + nt * 8 + g;
            Bh[nt][0] = sBh[t * 72 + nb];
            Bh[nt][1] = sBh[(t + 4) * 72 + nb];
            Bl[nt][0] = sBl[t * 72 + nb];
            Bl[nt][1] = sBl[(t + 4) * 72 + nb];
        }
#pragma unroll
        for (int mt = 0; mt < 2; mt++)
#pragma unroll
            for (int nt = 0; nt < 4; nt++) {
                MMA_BF16(c[mt][nt], Ah[mt], Bh[nt][0], Bh[nt][1]);
                MMA_BF16(c[mt][nt], Ah[mt], Bl[nt][0], Bl[nt][1]);
                MMA_BF16(c[mt][nt], Al[mt], Bh[nt][0], Bh[nt][1]);
            }
    }
}

#define GEMM_BF_SMEM                                                          \
    __shared__ unsigned sAh[8 * 136], sAl[8 * 136];                           \
    __shared__ unsigned sBh[8 * 72],  sBl[8 * 72];

__global__ void __launch_bounds__(256) qkvg_mma(const float* __restrict__ A,
                                                const float* __restrict__ gw,
                                                const float* __restrict__ bw,
                                                const float* __restrict__ wq,
                                                const float* __restrict__ wk,
                                                const float* __restrict__ wv,
                                                const float* __restrict__ wg,
                                                const float* __restrict__ bg,
                                                float qscale) {
    GEMM_BF_SMEM
    int zi = blockIdx.z;
    const float* B = (zi == 0) ? wq : (zi == 1) ? wk : (zi == 2) ? wv : wg;
    float* O = (zi == 0) ? g_q : (zi == 1) ? g_k : (zi == 2) ? g_v : g_gate;

    float c[2][4][4] = {};
    gemm_core_bf<1>(A, B, gw, bw, c, sAh, sAl, sBh, sBl);

    int lane = threadIdx.x & 31, w = threadIdx.x >> 5;
    int wm = w & 3, wn = w >> 2;
    int g = lane >> 2, t = lane & 3;
    int m0 = blockIdx.y * 128, n0 = blockIdx.x * 64;
#pragma unroll
    for (int mt = 0; mt < 2; mt++) {
        int r0 = m0 + wm * 32 + mt * 16 + g;
#pragma unroll
        for (int nt = 0; nt < 4; nt++) {
            int col = n0 + wn * 32 + nt * 8 + 2 * t;
            float v0 = c[mt][nt][0], v1 = c[mt][nt][1];
            float v2 = c[mt][nt][2], v3 = c[mt][nt][3];
            if (zi == 0) { v0 *= qscale; v1 *= qscale; v2 *= qscale; v3 *= qscale; }
            if (zi == 3) {
                float2 bb = *(const float2*)&bg[col];
                v0 = 1.f / (1.f + __expf(-(v0 + bb.x)));
                v1 = 1.f / (1.f + __expf(-(v1 + bb.y)));
                v2 = 1.f / (1.f + __expf(-(v2 + bb.x)));
                v3 = 1.f / (1.f + __expf(-(v3 + bb.y)));
            }
            *(float2*)&O[(size_t)r0 * CQ + col]       = make_float2(v0, v1);
            *(float2*)&O[(size_t)(r0 + 8) * CQ + col] = make_float2(v2, v3);
        }
    }
}

__global__ void __launch_bounds__(256) out_mma(const float* __restrict__ A,
                                               const float* __restrict__ B,
                                               float* __restrict__ C,
                                               const float* __restrict__ bias) {
    GEMM_BF_SMEM
    float c[2][4][4] = {};
    gemm_core_bf<0>(A, B, (const float*)0, (const float*)0, c, sAh, sAl, sBh, sBl);

    int lane = threadIdx.x & 31, w = threadIdx.x >> 5;
    int wm = w & 3, wn = w >> 2;
    int g = lane >> 2, t = lane & 3;
    int m0 = blockIdx.y * 128, n0 = blockIdx.x * 64;
#pragma unroll
    for (int mt = 0; mt < 2; mt++) {
        int r0 = m0 + wm * 32 + mt * 16 + g;
#pragma unroll
        for (int nt = 0; nt < 4; nt++) {
            int col = n0 + wn * 32 + nt * 8 + 2 * t;
            float2 bb = *(const float2*)&bias[col];
            *(float2*)&C[(size_t)r0 * CQ + col] =
                make_float2(c[mt][nt][0] + bb.x, c[mt][nt][1] + bb.y);
            *(float2*)&C[(size_t)(r0 + 8) * CQ + col] =
                make_float2(c[mt][nt][2] + bb.x, c[mt][nt][3] + bb.y);
        }
    }
}

// ================= flash attention v2: no-max softmax, f16x2 exp, f16 PV, l via ones-column =================
// smem: Ks[2][64*68] floats | Vs2[2][32 pairs * 56 words] half2 (cols 0..47 data, col 48 ones, 49..55 zero)
#define VSTR 56
__global__ void __launch_bounds__(256) flash_mma() {
    extern __shared__ float fsm[];

    int tid = threadIdx.x, w = tid >> 5, lane = tid & 31;
    int hh = w >> 2, wl = w & 3;
    int g = lane >> 2, t = lane & 3;

    float* Ks = fsm + hh * 4352;
    unsigned* Vs2 = (unsigned*)(fsm + 8704) + hh * (32 * VSTR);

    int h  = blockIdx.y * 2 + hh;
    int i0 = blockIdx.x * 64;
    int irow = i0 + wl * 16 + g;

    // persistent Q fragments (tf32)
    unsigned aq[6][4];
    {
        const float* q0 = g_q + (size_t)irow * CQ + h * HD;
        const float* q8 = q0 + 8 * CQ;
#pragma unroll
        for (int ks = 0; ks < 6; ks++) {
            aq[ks][0] = f2tf(q0[ks * 8 + t]);
            aq[ks][1] = f2tf(q8[ks * 8 + t]);
            aq[ks][2] = f2tf(q0[ks * 8 + t + 4]);
            aq[ks][3] = f2tf(q8[ks * 8 + t + 4]);
        }
    }

    // init ones column (col 48) and zero pad (49..55) — written once, never overwritten
    for (int e = tid; e < 512; e += 256) {
        int hd2 = e >> 8, p = (e >> 3) & 31, cix = e & 7;
        unsigned* Vd2 = (unsigned*)(fsm + 8704) + hd2 * (32 * VSTR);
        Vd2[p * VSTR + 48 + cix] = (cix == 0) ? 0x3C003C00u : 0u;
    }

    const __half* scA = g_sc + ((size_t)irow * NH + h) * NTOK;
    const __half* scB = scA + (size_t)8 * NH * NTOK;

    float o[7][4] = {};
    const float L2E = 1.44269504088896f;

    for (int jt = 0; jt < 16; jt++) {
        int j0 = jt * 64;
        __syncthreads();

        // bias (half) direct to S registers
        float s[8][4];
#pragma unroll
        for (int nt = 0; nt < 8; nt++) {
            float2 bA = __half22float2(*(const __half2*)&scA[j0 + nt * 8 + 2 * t]);
            float2 bB = __half22float2(*(const __half2*)&scB[j0 + nt * 8 + 2 * t]);
            s[nt][0] = bA.x; s[nt][1] = bA.y; s[nt][2] = bB.x; s[nt][3] = bB.y;
        }

        // K tiles (tf32 floats), both heads
#pragma unroll
        for (int e = tid; e < 1536; e += 256) {
            int hd2 = (e >= 768);
            int e2 = e - hd2 * 768;
            int r = e2 / 12, cc = (e2 % 12) * 4;
            int hl = blockIdx.y * 2 + hd2;
            float* Kd = fsm + hd2 * 4352;
            float4 kv = *(const float4*)&g_k[(size_t)(j0 + r) * CQ + hl * HD + cc];
            Kd[r * 68 + cc + 0] = tf32f(kv.x); Kd[r * 68 + cc + 1] = tf32f(kv.y);
            Kd[r * 68 + cc + 2] = tf32f(kv.z); Kd[r * 68 + cc + 3] = tf32f(kv.w);
        }
        // V tiles (half2 row-pairs), both heads
#pragma unroll
        for (int e = tid; e < 768; e += 256) {
            int hd2 = (e >= 384);
            int e2 = e - hd2 * 384;
            int p = e2 / 12, ccg = (e2 % 12) * 4;
            int hl = blockIdx.y * 2 + hd2;
            unsigned* Vd2 = (unsigned*)(fsm + 8704) + hd2 * (32 * VSTR);
            const float* vr = &g_v[(size_t)(j0 + 2 * p) * CQ + hl * HD + ccg];
            float4 r0 = *(const float4*)vr;
            float4 r1 = *(const float4*)(vr + CQ);
            __half2 p0 = __floats2half2_rn(r0.x, r1.x);
            __half2 p1 = __floats2half2_rn(r0.y, r1.y);
            __half2 p2 = __floats2half2_rn(r0.z, r1.z);
            __half2 p3 = __floats2half2_rn(r0.w, r1.w);
            uint4 stv = make_uint4(*(unsigned*)&p0, *(unsigned*)&p1,
                                   *(unsigned*)&p2, *(unsigned*)&p3);
            *(uint4*)&Vd2[p * VSTR + ccg] = stv;
        }
        __syncthreads();

        // S += Q K^T (tf32)
#pragma unroll
        for (int ks = 0; ks < 6; ks++) {
#pragma unroll
            for (int nt = 0; nt < 8; nt++) {
                unsigned b0 = su(Ks[(nt * 8 + g) * 68 + ks * 8 + t]);
                unsigned b1 = su(Ks[(nt * 8 + g) * 68 + ks * 8 + t + 4]);
                MMA_TF32(s[nt], aq[ks], b0, b1);
            }
        }

        // P = exp(S) via ex2.approx.f16x2 (no max subtraction; masked -> underflow to 0)
        unsigned pA2[8], pB2[8];
#pragma unroll
        for (int nt = 0; nt < 8; nt++) {
            __half2 eA = h2exp2(__floats2half2_rn(s[nt][0] * L2E, s[nt][1] * L2E));
            __half2 eB = h2exp2(__floats2half2_rn(s[nt][2] * L2E, s[nt][3] * L2E));
            pA2[nt] = *(unsigned*)&eA;
            pB2[nt] = *(unsigned*)&eB;
        }

        // O += P V  (f16 mma, 4 k-chunks x 7 nd tiles; nd=6 is the ones column -> row sums)
#pragma unroll
        for (int cchunk = 0; cchunk < 4; cchunk++) {
#pragma unroll
            for (int nd = 0; nd < 7; nd++) {
                unsigned b0 = Vs2[(cchunk * 8 + t) * VSTR + nd * 8 + g];
                unsigned b1 = Vs2[(cchunk * 8 + t + 4) * VSTR + nd * 8 + g];
                MMA_F16(o[nd], pA2[2 * cchunk], pB2[2 * cchunk],
                        pA2[2 * cchunk + 1], pB2[2 * cchunk + 1], b0, b1);
            }
        }
    }

    // l = row sums from ones-column (held at lanes t==0)
    float lA = __shfl_sync(0xffffffffu, o[6][0], lane & ~3);
    float lB = __shfl_sync(0xffffffffu, o[6][2], lane & ~3);
    float iA = 1.f / lA, iB = 1.f / lB;
#pragma unroll
    for (int nd = 0; nd < 6; nd++) {
        int col = h * HD + nd * 8 + 2 * t;
        size_t iAx = (size_t)irow * CQ + col;
        size_t iBx = (size_t)(irow + 8) * CQ + col;
        float2 ga = *(const float2*)&g_gate[iAx];
        float2 gb = *(const float2*)&g_gate[iBx];
        *(float2*)&g_og[iAx] = make_float2(o[nd][0] * iA * ga.x, o[nd][1] * iA * ga.y);
        *(float2*)&g_og[iBx] = make_float2(o[nd][2] * iB * gb.x, o[nd][3] * iB * gb.y);
    }
}

// ------------------------------- launch -------------------------------
#define PB_SMEM ((128 * 132 + 16 * 132 + 16 * 132 + 256) * 4)
#define FL_SMEM ((8704 + 2 * 32 * VSTR) * 4)

extern "C" void kernel_launch(void* const* d_in, const int* in_sizes, int n_in,
                              void* d_out, int out_size) {
    const float* a    = (const float*)d_in[0];
    const float* z    = (const float*)d_in[1];
    const float* mask = (const float*)d_in[2];
    const float* ga   = (const float*)d_in[3];
    const float* ba   = (const float*)d_in[4];
    const float* gz   = (const float*)d_in[5];
    const float* bz   = (const float*)d_in[6];
    const float* wz   = (const float*)d_in[7];
    const float* wq   = (const float*)d_in[8];
    const float* wk   = (const float*)d_in[9];
    const float* wv   = (const float*)d_in[10];
    const float* wg   = (const float*)d_in[11];
    const float* bg   = (const float*)d_in[12];
    const float* wo   = (const float*)d_in[13];
    const float* bo   = (const float*)d_in[14];
    float* out = (float*)d_out;

    float *p_og;
    cudaGetSymbolAddress((void**)&p_og, g_og);

    static int init_done = 0;
    if (!init_done) {
        cudaFuncSetAttribute(flash_mma, cudaFuncAttributeMaxDynamicSharedMemorySize, FL_SMEM);
        cudaFuncSetAttribute(pair_mma,  cudaFuncAttributeMaxDynamicSharedMemorySize, PB_SMEM);
        init_done = 1;
    }

    a_stats_kernel<<<NTOK, 256>>>(a);
    prep_kernel<<<1, 128>>>(gz, bz, wz);
    pair_mma<<<dim3(NTOK / 128, NTOK), 256, PB_SMEM>>>(z, mask);

    float qscale = 1.0f / sqrtf((float)HD);
    qkvg_mma<<<dim3(CQ / 64, NTOK / 128, 4), 256>>>(a, ga, ba, wq, wk, wv, wg, bg, qscale);

    flash_mma<<<dim3(NTOK / 64, NH / 2), 256, FL_SMEM>>>();

    out_mma<<<dim3(CQ / 64, NTOK / 128), 256>>>(p_og, wo, out, bo);
}